// round 13
// baseline (speedup 1.0000x reference)
#include <cuda_runtime.h>
#include <cuda_bf16.h>
#include <math.h>
#include <stdint.h>

// Problem constants
#define B_  2
#define T_  2048
#define D_  2048
#define H_  16
#define DK_ 128
#define MT_ (B_ * T_)            // 4096 rows

// ---------------------------------------------------------------------------
// Scratch (static device globals; no allocation allowed)
// ---------------------------------------------------------------------------
__device__ float g_qkv[(size_t)MT_ * 3 * D_];              // [4096, 6144]
__device__ float g_x32[(size_t)MT_ * D_];                  // x, tf32-rna
__device__ float g_wqt32[(size_t)3 * D_ * D_];             // Wqkv^T, tf32-rna
__device__ float g_wot32[(size_t)D_ * D_];                 // Wout^T, tf32-rna
__device__ float g_ao32[(size_t)MT_ * D_];                 // attn out, tf32-rna

// attention operands
__device__ float g_qf[(size_t)B_ * H_ * T_ * DK_];            // Q tf32-rna [B,H,T,DK]
__device__ float g_kf[(size_t)B_ * H_ * T_ * DK_];            // K tf32-rna
__device__ __nv_bfloat16 g_vthi[(size_t)B_ * H_ * DK_ * T_];  // V^T hi [B,H,DK,T]
__device__ __nv_bfloat16 g_vtlo[(size_t)B_ * H_ * DK_ * T_];

// ---------------------------------------------------------------------------
// PTX helpers (baseline PTX only — harness PTX target is sm_103, no tcgen05)
// ---------------------------------------------------------------------------
__device__ __forceinline__ uint32_t smem_u32(const void* p) {
    uint32_t a;
    asm("{ .reg .u64 t; cvta.to.shared.u64 t, %1; cvt.u32.u64 %0, t; }"
        : "=r"(a) : "l"(p));
    return a;
}

#define CP16(dst, src) \
    asm volatile("cp.async.cg.shared.global [%0], [%1], 16;" :: "r"(dst), "l"(src))
#define CP_COMMIT() asm volatile("cp.async.commit_group;" ::: "memory")
#define CP_WAITG(n) asm volatile("cp.async.wait_group %0;" :: "n"(n) : "memory")

#define LDSM4(r0, r1, r2, r3, addr) \
    asm volatile("ldmatrix.sync.aligned.m8n8.x4.shared.b16 {%0,%1,%2,%3}, [%4];" \
                 : "=r"(r0), "=r"(r1), "=r"(r2), "=r"(r3) : "r"(addr))

#define MMA16816(c, a, b0, b1) \
    asm volatile("mma.sync.aligned.m16n8k16.row.col.f32.bf16.bf16.f32 " \
                 "{%0,%1,%2,%3}, {%4,%5,%6,%7}, {%8,%9}, {%0,%1,%2,%3};" \
                 : "+f"((c)[0]), "+f"((c)[1]), "+f"((c)[2]), "+f"((c)[3]) \
                 : "r"((a)[0]), "r"((a)[1]), "r"((a)[2]), "r"((a)[3]), \
                   "r"(b0), "r"(b1))

// NOTE: A regs r1/r2 from ldmatrix must be swapped for the tf32 fragment
// (ldmatrix gives a0,a2,a1,a3 with our addressing).
#define MMA1688TF_SW(c, a, b0, b1) \
    asm volatile("mma.sync.aligned.m16n8k8.row.col.f32.tf32.tf32.f32 " \
                 "{%0,%1,%2,%3}, {%4,%5,%6,%7}, {%8,%9}, {%0,%1,%2,%3};" \
                 : "+f"((c)[0]), "+f"((c)[1]), "+f"((c)[2]), "+f"((c)[3]) \
                 : "r"((a)[0]), "r"((a)[2]), "r"((a)[1]), "r"((a)[3]), \
                   "r"(b0), "r"(b1))

__device__ __forceinline__ float rna_tf32(float x) {
    uint32_t r, i = __float_as_uint(x);
    asm("cvt.rna.tf32.f32 %0, %1;" : "=r"(r) : "r"(i));
    return __uint_as_float(r);
}

// Hardware MUFU exp2 (ex2.approx): 1 instruction vs ~20 for accurate exp2f.
// rel err ~2^-22; args here are always <= 0 or -inf (-inf -> 0). Safe.
__device__ __forceinline__ float ex2a(float x) {
    float r;
    asm("ex2.approx.f32 %0, %1;" : "=f"(r) : "f"(x));
    return r;
}

// ---------------------------------------------------------------------------
// Precision split helpers
// ---------------------------------------------------------------------------
__device__ __forceinline__ void split_one(float x, __nv_bfloat16& h, __nv_bfloat16& l) {
    h = __float2bfloat16_rn(x);
    l = __float2bfloat16_rn(x - __bfloat162float(h));
}

__device__ __forceinline__ void split2pack(float a, float b, uint32_t& hr, uint32_t& lr) {
    __nv_bfloat16 ah = __float2bfloat16_rn(a);
    __nv_bfloat16 bh = __float2bfloat16_rn(b);
    __nv_bfloat16 al = __float2bfloat16_rn(a - __bfloat162float(ah));
    __nv_bfloat16 bl = __float2bfloat16_rn(b - __bfloat162float(bh));
    __nv_bfloat162 hv; hv.x = ah; hv.y = bh;
    __nv_bfloat162 lv; lv.x = al; lv.y = bl;
    hr = *reinterpret_cast<uint32_t*>(&hv);
    lr = *reinterpret_cast<uint32_t*>(&lv);
}

// Elementwise tf32-rna copy
__global__ __launch_bounds__(256) void rna_copy_kernel(
    const float* __restrict__ X, float* __restrict__ Y, int n4)
{
    int i = blockIdx.x * blockDim.x + threadIdx.x;
    if (i >= n4) return;
    float4 v = *(const float4*)&X[(size_t)i * 4];
    v.x = rna_tf32(v.x); v.y = rna_tf32(v.y);
    v.z = rna_tf32(v.z); v.w = rna_tf32(v.w);
    *(float4*)&Y[(size_t)i * 4] = v;
}

// Transpose + rna: W[K,N] fp32 row-major -> W^T[N,K] tf32-rna fp32
__global__ __launch_bounds__(256) void transpose_rna_kernel(
    const float* __restrict__ W, float* __restrict__ Wt, int K, int N)
{
    __shared__ float t[32][33];
    const int n0 = blockIdx.x * 32, k0 = blockIdx.y * 32;
    const int tx = threadIdx.x, ty = threadIdx.y;   // 32 x 8
#pragma unroll
    for (int i = 0; i < 4; i++)
        t[ty + 8 * i][tx] = W[(size_t)(k0 + ty + 8 * i) * N + n0 + tx];
    __syncthreads();
#pragma unroll
    for (int i = 0; i < 4; i++)
        Wt[(size_t)(n0 + ty + 8 * i) * K + k0 + tx] = rna_tf32(t[tx][ty + 8 * i]);
}

// ---------------------------------------------------------------------------
// TF32 warp-MMA GEMM (exact R6 version — validated fastest)
// ---------------------------------------------------------------------------
#define GT_STAGES 3
#define GT_ROW_BYTES 144
#define GT_MAT_BYTES (128 * GT_ROW_BYTES)          // 18432
#define GT_STAGE_BYTES (2 * GT_MAT_BYTES)          // 36864
#define GT_SMEM (GT_STAGES * GT_STAGE_BYTES)       // 110592

__device__ __forceinline__ void gt_load_stage(
    uint32_t sbase, const float* __restrict__ A, const float* __restrict__ Bm,
    int m0, int n0, int K, int kb, int tid)
{
#pragma unroll
    for (int i = 0; i < 8; i++) {
        const int idx = tid + 256 * i;          // 0..2047
        const int row = (idx >> 3) & 127;       // 0..127
        const int mat = idx >> 10;              // 0: A, 1: B
        const int seg = idx & 7;                // 16B segment (4 floats)
        const uint32_t d = (uint32_t)(mat * GT_MAT_BYTES + row * GT_ROW_BYTES + seg * 16);
        const float* src = (mat == 0)
            ? (A  + (size_t)(m0 + row) * K + kb + seg * 4)
            : (Bm + (size_t)(n0 + row) * K + kb + seg * 4);
        CP16(sbase + d, src);
    }
}

__global__ __launch_bounds__(256) void gemm_tf32(
    const float* __restrict__ A, const float* __restrict__ Bm,
    float* __restrict__ C, int M, int N, int K)
{
    extern __shared__ char dsm[];
    const uint32_t sbase = smem_u32(dsm);

    const int tid  = threadIdx.x;
    const int wid  = tid >> 5;
    const int lane = tid & 31;
    const int m0 = blockIdx.y * 128;
    const int n0 = blockIdx.x * 128;
    const int wm = (wid & 1) * 64;
    const int wn = (wid >> 1) * 32;

    const uint32_t lr   = lane & 7;
    const uint32_t lmat = lane >> 3;          // 0..3 matrix select
    const uint32_t rowsel = (lmat >> 1) * 8 + lr;
    const uint32_t quad   = (lmat & 1) * 16;

    float acc[4][4][4];
#pragma unroll
    for (int mt = 0; mt < 4; mt++)
#pragma unroll
        for (int nt = 0; nt < 4; nt++)
#pragma unroll
            for (int e = 0; e < 4; e++) acc[mt][nt][e] = 0.f;

    const int nk = K / 32;

#pragma unroll
    for (int s = 0; s < GT_STAGES - 1; s++) {
        gt_load_stage(sbase + s * GT_STAGE_BYTES, A, Bm, m0, n0, K, s * 32, tid);
        CP_COMMIT();
    }

    for (int kb = 0; kb < nk; kb++) {
        CP_WAITG(GT_STAGES - 2);
        __syncthreads();

        if (kb + GT_STAGES - 1 < nk) {
            gt_load_stage(sbase + ((kb + GT_STAGES - 1) % GT_STAGES) * GT_STAGE_BYTES,
                          A, Bm, m0, n0, K, (kb + GT_STAGES - 1) * 32, tid);
        }
        CP_COMMIT();

        const uint32_t aS = sbase + (kb % GT_STAGES) * GT_STAGE_BYTES;
        const uint32_t bS = aS + GT_MAT_BYTES;

#pragma unroll
        for (int s = 0; s < 4; s++) {          // 4 k8 steps in BK=32
            uint32_t bf[2][4];
#pragma unroll
            for (int np = 0; np < 2; np++) {
                const uint32_t boff =
                    (uint32_t)((wn + np * 16 + rowsel) * GT_ROW_BYTES + quad + s * 32);
                LDSM4(bf[np][0], bf[np][1], bf[np][2], bf[np][3], bS + boff);
            }
#pragma unroll
            for (int mt = 0; mt < 4; mt++) {
                const uint32_t aoff =
                    (uint32_t)((wm + mt * 16 + rowsel) * GT_ROW_BYTES + quad + s * 32);
                uint32_t af[4];
                LDSM4(af[0], af[1], af[2], af[3], aS + aoff);
#pragma unroll
                for (int nt = 0; nt < 4; nt++) {
                    MMA1688TF_SW(acc[mt][nt], af,
                                 bf[nt >> 1][(nt & 1) * 2],
                                 bf[nt >> 1][(nt & 1) * 2 + 1]);
                }
            }
        }
    }

    const int r0 = lane >> 2;
    const int c0 = (lane & 3) * 2;
#pragma unroll
    for (int mt = 0; mt < 4; mt++) {
#pragma unroll
        for (int nt = 0; nt < 4; nt++) {
            const int row = m0 + wm + mt * 16 + r0;
            const int col = n0 + wn + nt * 8 + c0;
            float2 v0; v0.x = acc[mt][nt][0]; v0.y = acc[mt][nt][1];
            float2 v1; v1.x = acc[mt][nt][2]; v1.y = acc[mt][nt][3];
            *(float2*)&C[(size_t)row * N + col]       = v0;
            *(float2*)&C[(size_t)(row + 8) * N + col] = v1;
        }
    }
}

// ---------------------------------------------------------------------------
// RoPE: qkv fp32 -> Q,K tf32-rna fp32 [B,H,T,DK], V^T hi/lo bf16 [B,H,DK,T]
// ---------------------------------------------------------------------------
__global__ __launch_bounds__(256) void rope_kernel(
    const float* __restrict__ qkv, const float* __restrict__ freqs,
    float* __restrict__ Qf, float* __restrict__ Kf,
    __nv_bfloat16* __restrict__ Vth, __nv_bfloat16* __restrict__ Vtl)
{
    const int g = blockIdx.x * blockDim.x + threadIdx.x;
    const int total = B_ * T_ * H_ * (DK_ / 2);
    if (g >= total) return;
    const int j = g & 63;
    const int h = (g >> 6) & (H_ - 1);
    const int t = (g >> 10) & (T_ - 1);
    const int b = g >> 21;
    const int bh = b * H_ + h;

    const size_t row  = (size_t)b * T_ + t;
    const size_t base = row * (3 * D_) + (size_t)h * (3 * DK_);
    const float f = freqs[row * 64 + j];
    float s, c;
    sincosf(f, &s, &c);

    const float qr = qkv[base + 2 * j];
    const float qi = qkv[base + 2 * j + 1];
    const float kr = qkv[base + DK_ + 2 * j];
    const float ki = qkv[base + DK_ + 2 * j + 1];
    const float v0 = qkv[base + 2 * DK_ + 2 * j];
    const float v1 = qkv[base + 2 * DK_ + 2 * j + 1];

    const size_t ob = ((size_t)bh * T_ + t) * DK_ + 2 * j;
    float2 qv; qv.x = rna_tf32(qr * c - qi * s); qv.y = rna_tf32(qr * s + qi * c);
    float2 kv; kv.x = rna_tf32(kr * c - ki * s); kv.y = rna_tf32(kr * s + ki * c);
    *(float2*)&Qf[ob] = qv;
    *(float2*)&Kf[ob] = kv;

    __nv_bfloat16 vh, vl;
    const size_t vb0 = ((size_t)bh * DK_ + 2 * j) * T_ + t;
    split_one(v0, vh, vl);
    Vth[vb0] = vh; Vtl[vb0] = vl;
    split_one(v1, vh, vl);
    Vth[vb0 + T_] = vh; Vtl[vb0 + T_] = vl;
}

// ---------------------------------------------------------------------------
// Tensor-core flash attention (causal).
// S = Q K^T via single-pass tf32 (Q,K fp32-rna in smem).
// O += P V via bf16x3 (P packed from accumulators — validated R4 path).
// Softmax exponentials via MUFU ex2.approx (this round's change).
// CTA: 128 q-rows x one (b,h); 8 warps; K/V tiles 64 keys double-buffered.
// ---------------------------------------------------------------------------
#define AQ4_STRIDE 528           // 128 fp32 = 512B + 16 pad
#define AV_STRIDE  144           // 64 bf16 = 128B + 16 pad
#define A_Q     0                // 128 * 528 = 67584
#define A_KBASE 67584            // per stage 64 * 528 = 33792, x2
#define A_KSTAGE 33792
#define A_VBASE 135168           // per stage: hi 18432 + lo 18432 = 36864, x2
#define A_VHALF 18432
#define A_VSTAGE 36864
#define ATT_SMEM 208896

__device__ __forceinline__ void att_load_kv(
    uint32_t sb, int stage, int kt, int bh, int tid,
    const float* __restrict__ Kf,
    const __nv_bfloat16* __restrict__ Vth, const __nv_bfloat16* __restrict__ Vtl)
{
    const uint32_t kb = sb + A_KBASE + stage * A_KSTAGE;
    const uint32_t vb = sb + A_VBASE + stage * A_VSTAGE;
    const float* kg = Kf + ((size_t)bh * T_ + kt * 64) * DK_;
#pragma unroll
    for (int i = 0; i < 8; i++) {
        const int idx = tid + 256 * i;          // 0..2047
        const int row = idx >> 5, seg = idx & 31;
        CP16(kb + (uint32_t)(row * AQ4_STRIDE + seg * 16),
             kg + (size_t)row * DK_ + seg * 4);
    }
    const __nv_bfloat16* vhg = Vth + (size_t)bh * DK_ * T_ + (size_t)kt * 64;
    const __nv_bfloat16* vlg = Vtl + (size_t)bh * DK_ * T_ + (size_t)kt * 64;
#pragma unroll
    for (int i = 0; i < 4; i++) {
        const int idx = tid + 256 * i;          // 0..1023
        const int row = idx >> 3, seg = idx & 7;
        const uint32_t d = (uint32_t)(row * AV_STRIDE + seg * 16);
        CP16(vb + d,            vhg + (size_t)row * T_ + seg * 8);
        CP16(vb + A_VHALF + d,  vlg + (size_t)row * T_ + seg * 8);
    }
}

__global__ __launch_bounds__(256, 1) void attn_mma_kernel(
    const float* __restrict__ Qf, const float* __restrict__ Kf,
    const __nv_bfloat16* __restrict__ Vth, const __nv_bfloat16* __restrict__ Vtl,
    float* __restrict__ AO)
{
    extern __shared__ char asm_[];
    const uint32_t sb = smem_u32(asm_);

    const int qt = blockIdx.x, h = blockIdx.y, b = blockIdx.z;
    const int bh = b * H_ + h;
    const int q0 = qt * 128;
    const int tid = threadIdx.x, wid = tid >> 5, lane = tid & 31;
    const uint32_t lr = lane & 7, lmat = lane >> 3;
    const uint32_t rowsel = (lmat >> 1) * 8 + lr;
    const uint32_t quad   = (lmat & 1) * 16;

    // ---- prologue: load Q (fp32) + stage 0 K/V ----
    {
        const float* qg = Qf + ((size_t)bh * T_ + q0) * DK_;
#pragma unroll
        for (int i = 0; i < 16; i++) {
            const int idx = tid + 256 * i;      // 0..4095
            const int row = idx >> 5, seg = idx & 31;
            CP16(sb + A_Q + (uint32_t)(row * AQ4_STRIDE + seg * 16),
                 qg + (size_t)row * DK_ + seg * 4);
        }
        att_load_kv(sb, 0, 0, bh, tid, Kf, Vth, Vtl);
        CP_COMMIT();
    }

    float oacc[16][4];
#pragma unroll
    for (int nt = 0; nt < 16; nt++)
#pragma unroll
        for (int e = 0; e < 4; e++) oacc[nt][e] = 0.f;
    float m0 = -INFINITY, m1 = -INFINITY, l0 = 0.f, l1 = 0.f;
    const float csc = 0.08838834764831845f * 1.44269504089f;

    const int nkt = 2 * qt + 2;
    const int rowg0 = q0 + wid * 16 + (lane >> 2);
    const int rowg1 = rowg0 + 8;

    for (int kt = 0; kt < nkt; kt++) {
        if (kt + 1 < nkt) {
            att_load_kv(sb, (kt + 1) & 1, kt + 1, bh, tid, Kf, Vth, Vtl);
            CP_COMMIT();
            CP_WAITG(1);
        } else {
            CP_WAITG(0);
        }
        __syncthreads();

        const uint32_t kS  = sb + A_KBASE + (kt & 1) * A_KSTAGE;
        const uint32_t vbh = sb + A_VBASE + (kt & 1) * A_VSTAGE;
        const uint32_t vbl = vbh + A_VHALF;

        // ---- S = Q K^T (single-pass tf32) ----
        float sacc[8][4];
#pragma unroll
        for (int nt = 0; nt < 8; nt++)
#pragma unroll
            for (int e = 0; e < 4; e++) sacc[nt][e] = 0.f;

#pragma unroll
        for (int ks = 0; ks < 16; ks++) {      // 16 k8 steps over DK=128
            uint32_t af[4];
            LDSM4(af[0], af[1], af[2], af[3],
                  sb + A_Q + (uint32_t)((wid * 16 + rowsel) * AQ4_STRIDE +
                                        quad + ks * 32));
            uint32_t bf[4][4];
#pragma unroll
            for (int np = 0; np < 4; np++) {
                LDSM4(bf[np][0], bf[np][1], bf[np][2], bf[np][3],
                      kS + (uint32_t)((np * 16 + rowsel) * AQ4_STRIDE +
                                      quad + ks * 32));
            }
#pragma unroll
            for (int nt = 0; nt < 8; nt++) {
                MMA1688TF_SW(sacc[nt], af,
                             bf[nt >> 1][(nt & 1) * 2],
                             bf[nt >> 1][(nt & 1) * 2 + 1]);
            }
        }

        // ---- scale (+ causal mask on boundary tiles), log2 domain ----
        const bool need_mask = (kt >= 2 * qt);
#pragma unroll
        for (int nt = 0; nt < 8; nt++) {
            const int col = kt * 64 + nt * 8 + (lane & 3) * 2;
#pragma unroll
            for (int e = 0; e < 4; e++) {
                float z = sacc[nt][e] * csc;
                if (need_mask) {
                    const int cc = col + (e & 1);
                    const int rr = (e < 2) ? rowg0 : rowg1;
                    if (cc > rr) z = -INFINITY;
                }
                sacc[nt][e] = z;
            }
        }

        // ---- online softmax (MUFU ex2.approx) ----
        float mx0 = -INFINITY, mx1 = -INFINITY;
#pragma unroll
        for (int nt = 0; nt < 8; nt++) {
            mx0 = fmaxf(mx0, fmaxf(sacc[nt][0], sacc[nt][1]));
            mx1 = fmaxf(mx1, fmaxf(sacc[nt][2], sacc[nt][3]));
        }
        mx0 = fmaxf(mx0, __shfl_xor_sync(0xffffffffu, mx0, 1));
        mx0 = fmaxf(mx0, __shfl_xor_sync(0xffffffffu, mx0, 2));
        mx1 = fmaxf(mx1, __shfl_xor_sync(0xffffffffu, mx1, 1));
        mx1 = fmaxf(mx1, __shfl_xor_sync(0xffffffffu, mx1, 2));
        const float mn0 = fmaxf(m0, mx0), mn1 = fmaxf(m1, mx1);
        const float al0 = ex2a(m0 - mn0), al1 = ex2a(m1 - mn1);
        float rs0 = 0.f, rs1 = 0.f;
#pragma unroll
        for (int nt = 0; nt < 8; nt++) {
            sacc[nt][0] = ex2a(sacc[nt][0] - mn0);
            sacc[nt][1] = ex2a(sacc[nt][1] - mn0);
            sacc[nt][2] = ex2a(sacc[nt][2] - mn1);
            sacc[nt][3] = ex2a(sacc[nt][3] - mn1);
            rs0 += sacc[nt][0] + sacc[nt][1];
            rs1 += sacc[nt][2] + sacc[nt][3];
        }
        rs0 += __shfl_xor_sync(0xffffffffu, rs0, 1);
        rs0 += __shfl_xor_sync(0xffffffffu, rs0, 2);
        rs1 += __shfl_xor_sync(0xffffffffu, rs1, 1);
        rs1 += __shfl_xor_sync(0xffffffffu, rs1, 2);
        l0 = l0 * al0 + rs0;  m0 = mn0;
        l1 = l1 * al1 + rs1;  m1 = mn1;
#pragma unroll
        for (int nt = 0; nt < 16; nt++) {
            oacc[nt][0] *= al0; oacc[nt][1] *= al0;
            oacc[nt][2] *= al1; oacc[nt][3] *= al1;
        }

        // ---- pack P into bf16 A-fragments (hi/lo) ----
        uint32_t pah[4][4], pal[4][4];
#pragma unroll
        for (int ck = 0; ck < 4; ck++) {
            split2pack(sacc[2 * ck][0],     sacc[2 * ck][1],     pah[ck][0], pal[ck][0]);
            split2pack(sacc[2 * ck][2],     sacc[2 * ck][3],     pah[ck][1], pal[ck][1]);
            split2pack(sacc[2 * ck + 1][0], sacc[2 * ck + 1][1], pah[ck][2], pal[ck][2]);
            split2pack(sacc[2 * ck + 1][2], sacc[2 * ck + 1][3], pah[ck][3], pal[ck][3]);
        }

        // ---- O += P V (bf16x3) ----
#pragma unroll
        for (int ck = 0; ck < 4; ck++) {
#pragma unroll
            for (int nh = 0; nh < 8; nh++) {
                const uint32_t boff =
                    (uint32_t)((nh * 16 + (lmat >> 1) * 8 + lr) * AV_STRIDE +
                               (lmat & 1) * 16 + ck * 32);
                uint32_t vh[4], vl[4];
                LDSM4(vh[0], vh[1], vh[2], vh[3], vbh + boff);
                LDSM4(vl[0], vl[1], vl[2], vl[3], vbl + boff);
#pragma unroll
                for (int sub = 0; sub < 2; sub++) {
                    const int nt = nh * 2 + sub;
                    const uint32_t b0h = vh[sub * 2], b1h = vh[sub * 2 + 1];
                    const uint32_t b0l = vl[sub * 2], b1l = vl[sub * 2 + 1];
                    MMA16816(oacc[nt], pah[ck], b0h, b1h);
                    MMA16816(oacc[nt], pah[ck], b0l, b1l);
                    MMA16816(oacc[nt], pal[ck], b0h, b1h);
                }
            }
        }
        __syncthreads();
    }

    // ---- epilogue: normalize, tf32-rna, write fp32 [B,T,D] ----
    const float inv0 = 1.f / l0, inv1 = 1.f / l1;
#pragma unroll
    for (int nt = 0; nt < 16; nt++) {
        const int col = h * DK_ + nt * 8 + (lane & 3) * 2;
        const size_t o0 = ((size_t)b * T_ + rowg0) * D_ + col;
        const size_t o1 = ((size_t)b * T_ + rowg1) * D_ + col;
        float2 v0;
        v0.x = rna_tf32(oacc[nt][0] * inv0);
        v0.y = rna_tf32(oacc[nt][1] * inv0);
        float2 v1;
        v1.x = rna_tf32(oacc[nt][2] * inv1);
        v1.y = rna_tf32(oacc[nt][3] * inv1);
        *(float2*)&AO[o0] = v0;
        *(float2*)&AO[o1] = v1;
    }
}

// ---------------------------------------------------------------------------
// Launch
// ---------------------------------------------------------------------------
extern "C" void kernel_launch(void* const* d_in, const int* in_sizes, int n_in,
                              void* d_out, int out_size)
{
    const float* x     = (const float*)d_in[0];
    const float* freqs = (const float*)d_in[1];
    const float* Wqkv  = (const float*)d_in[2];
    const float* Wout  = (const float*)d_in[3];
    float* out = (float*)d_out;

    float *qkv, *x32, *wqt32, *wot32, *ao32, *qf, *kf;
    __nv_bfloat16 *vth, *vtl;
    cudaGetSymbolAddress((void**)&qkv,   g_qkv);
    cudaGetSymbolAddress((void**)&x32,   g_x32);
    cudaGetSymbolAddress((void**)&wqt32, g_wqt32);
    cudaGetSymbolAddress((void**)&wot32, g_wot32);
    cudaGetSymbolAddress((void**)&ao32,  g_ao32);
    cudaGetSymbolAddress((void**)&qf,  g_qf);
    cudaGetSymbolAddress((void**)&kf,  g_kf);
    cudaGetSymbolAddress((void**)&vth, g_vthi);
    cudaGetSymbolAddress((void**)&vtl, g_vtlo);

    cudaFuncSetAttribute(gemm_tf32,
                         cudaFuncAttributeMaxDynamicSharedMemorySize, GT_SMEM);
    cudaFuncSetAttribute(attn_mma_kernel,
                         cudaFuncAttributeMaxDynamicSharedMemorySize, ATT_SMEM);

    // 1) tf32-rna prep
    rna_copy_kernel<<<(MT_ * D_ / 4 + 255) / 256, 256>>>(x, x32, MT_ * D_ / 4);
    transpose_rna_kernel<<<dim3(3 * D_ / 32, D_ / 32), dim3(32, 8)>>>(
        Wqkv, wqt32, D_, 3 * D_);
    transpose_rna_kernel<<<dim3(D_ / 32, D_ / 32), dim3(32, 8)>>>(
        Wout, wot32, D_, D_);

    // 2) QKV projection (tf32)
    gemm_tf32<<<dim3(3 * D_ / 128, MT_ / 128), 256, GT_SMEM>>>(
        x32, wqt32, qkv, MT_, 3 * D_, D_);

    // 3) RoPE + head split (Q,K fp32-rna; V hi/lo bf16, transposed)
    {
        const int total = B_ * T_ * H_ * (DK_ / 2);
        rope_kernel<<<(total + 255) / 256, 256>>>(qkv, freqs, qf, kf, vth, vtl);
    }

    // 4) tensor-core causal flash attention (S tf32, PV bf16x3, MUFU softmax)
    attn_mma_kernel<<<dim3(T_ / 128, H_, B_), 256, ATT_SMEM>>>(
        qf, kf, vth, vtl, ao32);

    // 5) output projection (tf32)
    gemm_tf32<<<dim3(D_ / 128, MT_ / 128), 256, GT_SMEM>>>(
        ao32, wot32, out, MT_, D_, D_);
}

// round 16
// speedup vs baseline: 1.0923x; 1.0923x over previous
#include <cuda_runtime.h>
#include <cuda_bf16.h>
#include <math.h>
#include <stdint.h>

// Problem constants
#define B_  2
#define T_  2048
#define D_  2048
#define H_  16
#define DK_ 128
#define MT_ (B_ * T_)            // 4096 rows

// ---------------------------------------------------------------------------
// Scratch (static device globals; no allocation allowed)
// ---------------------------------------------------------------------------
__device__ float g_x32[(size_t)MT_ * D_];                  // x, tf32-rna
__device__ float g_wqt32[(size_t)3 * D_ * D_];             // Wqkv^T, tf32-rna
__device__ float g_wot32[(size_t)D_ * D_];                 // Wout^T, tf32-rna
__device__ float g_ao32[(size_t)MT_ * D_];                 // attn out, tf32-rna

// attention operands
__device__ float g_qf[(size_t)B_ * H_ * T_ * DK_];            // Q tf32-rna [B,H,T,DK]
__device__ float g_kf[(size_t)B_ * H_ * T_ * DK_];            // K tf32-rna
__device__ __nv_bfloat16 g_vthi[(size_t)B_ * H_ * DK_ * T_];  // V^T hi [B,H,DK,T]
__device__ __nv_bfloat16 g_vtlo[(size_t)B_ * H_ * DK_ * T_];

// ---------------------------------------------------------------------------
// PTX helpers (baseline PTX only — harness PTX target is sm_103, no tcgen05)
// ---------------------------------------------------------------------------
__device__ __forceinline__ uint32_t smem_u32(const void* p) {
    uint32_t a;
    asm("{ .reg .u64 t; cvta.to.shared.u64 t, %1; cvt.u32.u64 %0, t; }"
        : "=r"(a) : "l"(p));
    return a;
}

#define CP16(dst, src) \
    asm volatile("cp.async.cg.shared.global [%0], [%1], 16;" :: "r"(dst), "l"(src))
#define CP_COMMIT() asm volatile("cp.async.commit_group;" ::: "memory")
#define CP_WAITG(n) asm volatile("cp.async.wait_group %0;" :: "n"(n) : "memory")

#define LDSM4(r0, r1, r2, r3, addr) \
    asm volatile("ldmatrix.sync.aligned.m8n8.x4.shared.b16 {%0,%1,%2,%3}, [%4];" \
                 : "=r"(r0), "=r"(r1), "=r"(r2), "=r"(r3) : "r"(addr))

#define MMA16816(c, a, b0, b1) \
    asm volatile("mma.sync.aligned.m16n8k16.row.col.f32.bf16.bf16.f32 " \
                 "{%0,%1,%2,%3}, {%4,%5,%6,%7}, {%8,%9}, {%0,%1,%2,%3};" \
                 : "+f"((c)[0]), "+f"((c)[1]), "+f"((c)[2]), "+f"((c)[3]) \
                 : "r"((a)[0]), "r"((a)[1]), "r"((a)[2]), "r"((a)[3]), \
                   "r"(b0), "r"(b1))

// NOTE: A regs r1/r2 from ldmatrix must be swapped for the tf32 fragment
// (ldmatrix gives a0,a2,a1,a3 with our addressing).
#define MMA1688TF_SW(c, a, b0, b1) \
    asm volatile("mma.sync.aligned.m16n8k8.row.col.f32.tf32.tf32.f32 " \
                 "{%0,%1,%2,%3}, {%4,%5,%6,%7}, {%8,%9}, {%0,%1,%2,%3};" \
                 : "+f"((c)[0]), "+f"((c)[1]), "+f"((c)[2]), "+f"((c)[3]) \
                 : "r"((a)[0]), "r"((a)[2]), "r"((a)[1]), "r"((a)[3]), \
                   "r"(b0), "r"(b1))

__device__ __forceinline__ float rna_tf32(float x) {
    uint32_t r, i = __float_as_uint(x);
    asm("cvt.rna.tf32.f32 %0, %1;" : "=r"(r) : "r"(i));
    return __uint_as_float(r);
}

// Hardware MUFU exp2 (1 instruction). Args are <= 0 or -inf (-inf -> 0). Safe.
__device__ __forceinline__ float ex2a(float x) {
    float r;
    asm("ex2.approx.f32 %0, %1;" : "=f"(r) : "f"(x));
    return r;
}

// ---------------------------------------------------------------------------
// Precision split helpers
// ---------------------------------------------------------------------------
__device__ __forceinline__ void split_one(float x, __nv_bfloat16& h, __nv_bfloat16& l) {
    h = __float2bfloat16_rn(x);
    l = __float2bfloat16_rn(x - __bfloat162float(h));
}

__device__ __forceinline__ void split2pack(float a, float b, uint32_t& hr, uint32_t& lr) {
    __nv_bfloat16 ah = __float2bfloat16_rn(a);
    __nv_bfloat16 bh = __float2bfloat16_rn(b);
    __nv_bfloat16 al = __float2bfloat16_rn(a - __bfloat162float(ah));
    __nv_bfloat16 bl = __float2bfloat16_rn(b - __bfloat162float(bh));
    __nv_bfloat162 hv; hv.x = ah; hv.y = bh;
    __nv_bfloat162 lv; lv.x = al; lv.y = bl;
    hr = *reinterpret_cast<uint32_t*>(&hv);
    lr = *reinterpret_cast<uint32_t*>(&lv);
}

// Elementwise tf32-rna copy
__global__ __launch_bounds__(256) void rna_copy_kernel(
    const float* __restrict__ X, float* __restrict__ Y, int n4)
{
    int i = blockIdx.x * blockDim.x + threadIdx.x;
    if (i >= n4) return;
    float4 v = *(const float4*)&X[(size_t)i * 4];
    v.x = rna_tf32(v.x); v.y = rna_tf32(v.y);
    v.z = rna_tf32(v.z); v.w = rna_tf32(v.w);
    *(float4*)&Y[(size_t)i * 4] = v;
}

// Transpose + rna: W[K,N] fp32 row-major -> W^T[N,K] tf32-rna fp32
__global__ __launch_bounds__(256) void transpose_rna_kernel(
    const float* __restrict__ W, float* __restrict__ Wt, int K, int N)
{
    __shared__ float t[32][33];
    const int n0 = blockIdx.x * 32, k0 = blockIdx.y * 32;
    const int tx = threadIdx.x, ty = threadIdx.y;   // 32 x 8
#pragma unroll
    for (int i = 0; i < 4; i++)
        t[ty + 8 * i][tx] = W[(size_t)(k0 + ty + 8 * i) * N + n0 + tx];
    __syncthreads();
#pragma unroll
    for (int i = 0; i < 4; i++)
        Wt[(size_t)(n0 + ty + 8 * i) * K + k0 + tx] = rna_tf32(t[tx][ty + 8 * i]);
}

// ---------------------------------------------------------------------------
// Shared GEMM tile machinery (R6-validated)
// ---------------------------------------------------------------------------
#define GT_STAGES 3
#define GT_ROW_BYTES 144
#define GT_MAT_BYTES (128 * GT_ROW_BYTES)          // 18432
#define GT_STAGE_BYTES (2 * GT_MAT_BYTES)          // 36864
#define GT_SMEM (GT_STAGES * GT_STAGE_BYTES)       // 110592

__device__ __forceinline__ void gt_load_stage(
    uint32_t sbase, const float* __restrict__ A, const float* __restrict__ Bm,
    int m0, int n0, int K, int kb, int tid)
{
#pragma unroll
    for (int i = 0; i < 8; i++) {
        const int idx = tid + 256 * i;          // 0..2047
        const int row = (idx >> 3) & 127;       // 0..127
        const int mat = idx >> 10;              // 0: A, 1: B
        const int seg = idx & 7;                // 16B segment (4 floats)
        const uint32_t d = (uint32_t)(mat * GT_MAT_BYTES + row * GT_ROW_BYTES + seg * 16);
        const float* src = (mat == 0)
            ? (A  + (size_t)(m0 + row) * K + kb + seg * 4)
            : (Bm + (size_t)(n0 + row) * K + kb + seg * 4);
        CP16(sbase + d, src);
    }
}

// Mainloop body shared by both GEMM kernels: accumulates the 128x128 CTA tile.
__device__ __forceinline__ void gt_mainloop(
    uint32_t sbase, const float* __restrict__ A, const float* __restrict__ Bm,
    int m0, int n0, int K, int tid, int wm, int wn,
    uint32_t rowsel, uint32_t quad, float acc[4][4][4])
{
#pragma unroll
    for (int mt = 0; mt < 4; mt++)
#pragma unroll
        for (int nt = 0; nt < 4; nt++)
#pragma unroll
            for (int e = 0; e < 4; e++) acc[mt][nt][e] = 0.f;

    const int nk = K / 32;

#pragma unroll
    for (int s = 0; s < GT_STAGES - 1; s++) {
        gt_load_stage(sbase + s * GT_STAGE_BYTES, A, Bm, m0, n0, K, s * 32, tid);
        CP_COMMIT();
    }

    for (int kb = 0; kb < nk; kb++) {
        CP_WAITG(GT_STAGES - 2);
        __syncthreads();

        if (kb + GT_STAGES - 1 < nk) {
            gt_load_stage(sbase + ((kb + GT_STAGES - 1) % GT_STAGES) * GT_STAGE_BYTES,
                          A, Bm, m0, n0, K, (kb + GT_STAGES - 1) * 32, tid);
        }
        CP_COMMIT();

        const uint32_t aS = sbase + (kb % GT_STAGES) * GT_STAGE_BYTES;
        const uint32_t bS = aS + GT_MAT_BYTES;

#pragma unroll
        for (int s = 0; s < 4; s++) {          // 4 k8 steps in BK=32
            uint32_t bf[2][4];
#pragma unroll
            for (int np = 0; np < 2; np++) {
                const uint32_t boff =
                    (uint32_t)((wn + np * 16 + rowsel) * GT_ROW_BYTES + quad + s * 32);
                LDSM4(bf[np][0], bf[np][1], bf[np][2], bf[np][3], bS + boff);
            }
#pragma unroll
            for (int mt = 0; mt < 4; mt++) {
                const uint32_t aoff =
                    (uint32_t)((wm + mt * 16 + rowsel) * GT_ROW_BYTES + quad + s * 32);
                uint32_t af[4];
                LDSM4(af[0], af[1], af[2], af[3], aS + aoff);
#pragma unroll
                for (int nt = 0; nt < 4; nt++) {
                    MMA1688TF_SW(acc[mt][nt], af,
                                 bf[nt >> 1][(nt & 1) * 2],
                                 bf[nt >> 1][(nt & 1) * 2 + 1]);
                }
            }
        }
    }
}

// ---------------------------------------------------------------------------
// Plain TF32 GEMM (out projection): C[M,N] = A[M,K] @ B[N,K]^T
// ---------------------------------------------------------------------------
__global__ __launch_bounds__(256, 2) void gemm_tf32(
    const float* __restrict__ A, const float* __restrict__ Bm,
    float* __restrict__ C, int M, int N, int K)
{
    extern __shared__ char dsm[];
    const uint32_t sbase = smem_u32(dsm);

    const int tid  = threadIdx.x;
    const int wid  = tid >> 5;
    const int lane = tid & 31;
    const int m0 = blockIdx.y * 128;
    const int n0 = blockIdx.x * 128;
    const int wm = (wid & 1) * 64;
    const int wn = (wid >> 1) * 32;
    const uint32_t lr   = lane & 7;
    const uint32_t lmat = lane >> 3;
    const uint32_t rowsel = (lmat >> 1) * 8 + lr;
    const uint32_t quad   = (lmat & 1) * 16;

    float acc[4][4][4];
    gt_mainloop(sbase, A, Bm, m0, n0, K, tid, wm, wn, rowsel, quad, acc);

    const int r0 = lane >> 2;
    const int c0 = (lane & 3) * 2;
#pragma unroll
    for (int mt = 0; mt < 4; mt++) {
#pragma unroll
        for (int nt = 0; nt < 4; nt++) {
            const int row = m0 + wm + mt * 16 + r0;
            const int col = n0 + wn + nt * 8 + c0;
            float2 v0; v0.x = acc[mt][nt][0]; v0.y = acc[mt][nt][1];
            float2 v1; v1.x = acc[mt][nt][2]; v1.y = acc[mt][nt][3];
            *(float2*)&C[(size_t)row * N + col]       = v0;
            *(float2*)&C[(size_t)(row + 8) * N + col] = v1;
        }
    }
}

// ---------------------------------------------------------------------------
// Fused QKV GEMM + RoPE epilogue.
// N-tiles (128 wide) align exactly with q/k/v chunks (384 = 3*128 per head):
//   tile_type = (n0/128) % 3  (0=q, 1=k, 2=v),  h = n0/384.
// Accumulator threads hold adjacent column pairs (2j, 2j+1) = RoPE pairs.
// q,k: rotate + tf32-rna -> Qf/Kf [B,H,T,DK].
// v:   bf16 hi/lo split -> Vth/Vtl [B,H,DK,T] (transposed).
// ---------------------------------------------------------------------------
__global__ __launch_bounds__(256, 2) void gemm_qkv_rope(
    const float* __restrict__ A, const float* __restrict__ Bm,
    const float* __restrict__ freqs,
    float* __restrict__ Qf, float* __restrict__ Kf,
    __nv_bfloat16* __restrict__ Vth, __nv_bfloat16* __restrict__ Vtl)
{
    extern __shared__ char dsm[];
    const uint32_t sbase = smem_u32(dsm);

    const int K = D_;
    const int tid  = threadIdx.x;
    const int wid  = tid >> 5;
    const int lane = tid & 31;
    const int m0 = blockIdx.y * 128;
    const int n0 = blockIdx.x * 128;
    const int wm = (wid & 1) * 64;
    const int wn = (wid >> 1) * 32;
    const uint32_t lr   = lane & 7;
    const uint32_t lmat = lane >> 3;
    const uint32_t rowsel = (lmat >> 1) * 8 + lr;
    const uint32_t quad   = (lmat & 1) * 16;

    float acc[4][4][4];
    gt_mainloop(sbase, A, Bm, m0, n0, K, tid, wm, wn, rowsel, quad, acc);

    const int tt = (n0 >> 7) % 3;            // 0=q, 1=k, 2=v
    const int h  = n0 / 384;
    const int r0 = lane >> 2;
    const int c0 = (lane & 3) * 2;

    if (tt < 2) {
        float* dst = (tt == 0) ? Qf : Kf;
#pragma unroll
        for (int mt = 0; mt < 4; mt++) {
#pragma unroll
            for (int nt = 0; nt < 4; nt++) {
                const int lc = wn + nt * 8 + c0;     // 0..126 even
                const int j  = lc >> 1;
#pragma unroll
                for (int half = 0; half < 2; half++) {
                    const int row = m0 + wm + mt * 16 + r0 + half * 8;
                    const int b = row >> 11;         // row / T_
                    const int t = row & (T_ - 1);
                    const float f = freqs[(size_t)row * 64 + j];
                    float s, c;
                    sincosf(f, &s, &c);
                    const float v0 = acc[mt][nt][half * 2];
                    const float v1 = acc[mt][nt][half * 2 + 1];
                    float2 o;
                    o.x = rna_tf32(v0 * c - v1 * s);
                    o.y = rna_tf32(v0 * s + v1 * c);
                    const size_t ob =
                        (((size_t)(b * H_ + h)) * T_ + t) * DK_ + lc;
                    *(float2*)&dst[ob] = o;
                }
            }
        }
    } else {
#pragma unroll
        for (int mt = 0; mt < 4; mt++) {
#pragma unroll
            for (int nt = 0; nt < 4; nt++) {
                const int lc = wn + nt * 8 + c0;
#pragma unroll
                for (int half = 0; half < 2; half++) {
                    const int row = m0 + wm + mt * 16 + r0 + half * 8;
                    const int b = row >> 11;
                    const int t = row & (T_ - 1);
                    const size_t vb =
                        ((size_t)(b * H_ + h) * DK_ + lc) * T_ + t;
                    __nv_bfloat16 vh, vl;
                    split_one(acc[mt][nt][half * 2], vh, vl);
                    Vth[vb] = vh;  Vtl[vb] = vl;
                    split_one(acc[mt][nt][half * 2 + 1], vh, vl);
                    Vth[vb + T_] = vh;  Vtl[vb + T_] = vl;
                }
            }
        }
    }
}

// ---------------------------------------------------------------------------
// Tensor-core flash attention (causal).
// S = Q K^T single-pass tf32; O += P V bf16x3; MUFU softmax.
// qt is REVERSED vs blockIdx.x so heaviest CTAs launch first.
// ---------------------------------------------------------------------------
#define AQ4_STRIDE 528           // 128 fp32 = 512B + 16 pad
#define AV_STRIDE  144           // 64 bf16 = 128B + 16 pad
#define A_Q     0                // 128 * 528 = 67584
#define A_KBASE 67584            // per stage 64 * 528 = 33792, x2
#define A_KSTAGE 33792
#define A_VBASE 135168           // per stage: hi 18432 + lo 18432 = 36864, x2
#define A_VHALF 18432
#define A_VSTAGE 36864
#define ATT_SMEM 208896

__device__ __forceinline__ void att_load_kv(
    uint32_t sb, int stage, int kt, int bh, int tid,
    const float* __restrict__ Kf,
    const __nv_bfloat16* __restrict__ Vth, const __nv_bfloat16* __restrict__ Vtl)
{
    const uint32_t kb = sb + A_KBASE + stage * A_KSTAGE;
    const uint32_t vb = sb + A_VBASE + stage * A_VSTAGE;
    const float* kg = Kf + ((size_t)bh * T_ + kt * 64) * DK_;
#pragma unroll
    for (int i = 0; i < 8; i++) {
        const int idx = tid + 256 * i;          // 0..2047
        const int row = idx >> 5, seg = idx & 31;
        CP16(kb + (uint32_t)(row * AQ4_STRIDE + seg * 16),
             kg + (size_t)row * DK_ + seg * 4);
    }
    const __nv_bfloat16* vhg = Vth + (size_t)bh * DK_ * T_ + (size_t)kt * 64;
    const __nv_bfloat16* vlg = Vtl + (size_t)bh * DK_ * T_ + (size_t)kt * 64;
#pragma unroll
    for (int i = 0; i < 4; i++) {
        const int idx = tid + 256 * i;          // 0..1023
        const int row = idx >> 3, seg = idx & 7;
        const uint32_t d = (uint32_t)(row * AV_STRIDE + seg * 16);
        CP16(vb + d,            vhg + (size_t)row * T_ + seg * 8);
        CP16(vb + A_VHALF + d,  vlg + (size_t)row * T_ + seg * 8);
    }
}

__global__ __launch_bounds__(256, 1) void attn_mma_kernel(
    const float* __restrict__ Qf, const float* __restrict__ Kf,
    const __nv_bfloat16* __restrict__ Vth, const __nv_bfloat16* __restrict__ Vtl,
    float* __restrict__ AO)
{
    extern __shared__ char asm_[];
    const uint32_t sb = smem_u32(asm_);

    const int qt = (gridDim.x - 1) - blockIdx.x;   // heaviest tiles first
    const int h = blockIdx.y, b = blockIdx.z;
    const int bh = b * H_ + h;
    const int q0 = qt * 128;
    const int tid = threadIdx.x, wid = tid >> 5, lane = tid & 31;
    const uint32_t lr = lane & 7, lmat = lane >> 3;
    const uint32_t rowsel = (lmat >> 1) * 8 + lr;
    const uint32_t quad   = (lmat & 1) * 16;

    // ---- prologue: load Q (fp32) + stage 0 K/V ----
    {
        const float* qg = Qf + ((size_t)bh * T_ + q0) * DK_;
#pragma unroll
        for (int i = 0; i < 16; i++) {
            const int idx = tid + 256 * i;      // 0..4095
            const int row = idx >> 5, seg = idx & 31;
            CP16(sb + A_Q + (uint32_t)(row * AQ4_STRIDE + seg * 16),
                 qg + (size_t)row * DK_ + seg * 4);
        }
        att_load_kv(sb, 0, 0, bh, tid, Kf, Vth, Vtl);
        CP_COMMIT();
    }

    float oacc[16][4];
#pragma unroll
    for (int nt = 0; nt < 16; nt++)
#pragma unroll
        for (int e = 0; e < 4; e++) oacc[nt][e] = 0.f;
    float m0 = -INFINITY, m1 = -INFINITY, l0 = 0.f, l1 = 0.f;
    const float csc = 0.08838834764831845f * 1.44269504089f;

    const int nkt = 2 * qt + 2;
    const int rowg0 = q0 + wid * 16 + (lane >> 2);
    const int rowg1 = rowg0 + 8;

    for (int kt = 0; kt < nkt; kt++) {
        if (kt + 1 < nkt) {
            att_load_kv(sb, (kt + 1) & 1, kt + 1, bh, tid, Kf, Vth, Vtl);
            CP_COMMIT();
            CP_WAITG(1);
        } else {
            CP_WAITG(0);
        }
        __syncthreads();

        const uint32_t kS  = sb + A_KBASE + (kt & 1) * A_KSTAGE;
        const uint32_t vbh = sb + A_VBASE + (kt & 1) * A_VSTAGE;
        const uint32_t vbl = vbh + A_VHALF;

        // ---- S = Q K^T (single-pass tf32) ----
        float sacc[8][4];
#pragma unroll
        for (int nt = 0; nt < 8; nt++)
#pragma unroll
            for (int e = 0; e < 4; e++) sacc[nt][e] = 0.f;

#pragma unroll
        for (int ks = 0; ks < 16; ks++) {      // 16 k8 steps over DK=128
            uint32_t af[4];
            LDSM4(af[0], af[1], af[2], af[3],
                  sb + A_Q + (uint32_t)((wid * 16 + rowsel) * AQ4_STRIDE +
                                        quad + ks * 32));
            uint32_t bf[4][4];
#pragma unroll
            for (int np = 0; np < 4; np++) {
                LDSM4(bf[np][0], bf[np][1], bf[np][2], bf[np][3],
                      kS + (uint32_t)((np * 16 + rowsel) * AQ4_STRIDE +
                                      quad + ks * 32));
            }
#pragma unroll
            for (int nt = 0; nt < 8; nt++) {
                MMA1688TF_SW(sacc[nt], af,
                             bf[nt >> 1][(nt & 1) * 2],
                             bf[nt >> 1][(nt & 1) * 2 + 1]);
            }
        }

        // ---- scale (+ causal mask on boundary tiles), log2 domain ----
        const bool need_mask = (kt >= 2 * qt);
#pragma unroll
        for (int nt = 0; nt < 8; nt++) {
            const int col = kt * 64 + nt * 8 + (lane & 3) * 2;
#pragma unroll
            for (int e = 0; e < 4; e++) {
                float z = sacc[nt][e] * csc;
                if (need_mask) {
                    const int cc = col + (e & 1);
                    const int rr = (e < 2) ? rowg0 : rowg1;
                    if (cc > rr) z = -INFINITY;
                }
                sacc[nt][e] = z;
            }
        }

        // ---- online softmax (MUFU) ----
        float mx0 = -INFINITY, mx1 = -INFINITY;
#pragma unroll
        for (int nt = 0; nt < 8; nt++) {
            mx0 = fmaxf(mx0, fmaxf(sacc[nt][0], sacc[nt][1]));
            mx1 = fmaxf(mx1, fmaxf(sacc[nt][2], sacc[nt][3]));
        }
        mx0 = fmaxf(mx0, __shfl_xor_sync(0xffffffffu, mx0, 1));
        mx0 = fmaxf(mx0, __shfl_xor_sync(0xffffffffu, mx0, 2));
        mx1 = fmaxf(mx1, __shfl_xor_sync(0xffffffffu, mx1, 1));
        mx1 = fmaxf(mx1, __shfl_xor_sync(0xffffffffu, mx1, 2));
        const float mn0 = fmaxf(m0, mx0), mn1 = fmaxf(m1, mx1);
        const float al0 = ex2a(m0 - mn0), al1 = ex2a(m1 - mn1);
        float rs0 = 0.f, rs1 = 0.f;
#pragma unroll
        for (int nt = 0; nt < 8; nt++) {
            sacc[nt][0] = ex2a(sacc[nt][0] - mn0);
            sacc[nt][1] = ex2a(sacc[nt][1] - mn0);
            sacc[nt][2] = ex2a(sacc[nt][2] - mn1);
            sacc[nt][3] = ex2a(sacc[nt][3] - mn1);
            rs0 += sacc[nt][0] + sacc[nt][1];
            rs1 += sacc[nt][2] + sacc[nt][3];
        }
        rs0 += __shfl_xor_sync(0xffffffffu, rs0, 1);
        rs0 += __shfl_xor_sync(0xffffffffu, rs0, 2);
        rs1 += __shfl_xor_sync(0xffffffffu, rs1, 1);
        rs1 += __shfl_xor_sync(0xffffffffu, rs1, 2);
        l0 = l0 * al0 + rs0;  m0 = mn0;
        l1 = l1 * al1 + rs1;  m1 = mn1;
#pragma unroll
        for (int nt = 0; nt < 16; nt++) {
            oacc[nt][0] *= al0; oacc[nt][1] *= al0;
            oacc[nt][2] *= al1; oacc[nt][3] *= al1;
        }

        // ---- pack P into bf16 A-fragments (hi/lo) ----
        uint32_t pah[4][4], pal[4][4];
#pragma unroll
        for (int ck = 0; ck < 4; ck++) {
            split2pack(sacc[2 * ck][0],     sacc[2 * ck][1],     pah[ck][0], pal[ck][0]);
            split2pack(sacc[2 * ck][2],     sacc[2 * ck][3],     pah[ck][1], pal[ck][1]);
            split2pack(sacc[2 * ck + 1][0], sacc[2 * ck + 1][1], pah[ck][2], pal[ck][2]);
            split2pack(sacc[2 * ck + 1][2], sacc[2 * ck + 1][3], pah[ck][3], pal[ck][3]);
        }

        // ---- O += P V (bf16x3) ----
#pragma unroll
        for (int ck = 0; ck < 4; ck++) {
#pragma unroll
            for (int nh = 0; nh < 8; nh++) {
                const uint32_t boff =
                    (uint32_t)((nh * 16 + (lmat >> 1) * 8 + lr) * AV_STRIDE +
                               (lmat & 1) * 16 + ck * 32);
                uint32_t vh[4], vl[4];
                LDSM4(vh[0], vh[1], vh[2], vh[3], vbh + boff);
                LDSM4(vl[0], vl[1], vl[2], vl[3], vbl + boff);
#pragma unroll
                for (int sub = 0; sub < 2; sub++) {
                    const int nt = nh * 2 + sub;
                    const uint32_t b0h = vh[sub * 2], b1h = vh[sub * 2 + 1];
                    const uint32_t b0l = vl[sub * 2], b1l = vl[sub * 2 + 1];
                    MMA16816(oacc[nt], pah[ck], b0h, b1h);
                    MMA16816(oacc[nt], pah[ck], b0l, b1l);
                    MMA16816(oacc[nt], pal[ck], b0h, b1h);
                }
            }
        }
        __syncthreads();
    }

    // ---- epilogue: normalize, tf32-rna, write fp32 [B,T,D] ----
    const float inv0 = 1.f / l0, inv1 = 1.f / l1;
#pragma unroll
    for (int nt = 0; nt < 16; nt++) {
        const int col = h * DK_ + nt * 8 + (lane & 3) * 2;
        const size_t o0 = ((size_t)b * T_ + rowg0) * D_ + col;
        const size_t o1 = ((size_t)b * T_ + rowg1) * D_ + col;
        float2 v0;
        v0.x = rna_tf32(oacc[nt][0] * inv0);
        v0.y = rna_tf32(oacc[nt][1] * inv0);
        float2 v1;
        v1.x = rna_tf32(oacc[nt][2] * inv1);
        v1.y = rna_tf32(oacc[nt][3] * inv1);
        *(float2*)&AO[o0] = v0;
        *(float2*)&AO[o1] = v1;
    }
}

// ---------------------------------------------------------------------------
// Launch
// ---------------------------------------------------------------------------
extern "C" void kernel_launch(void* const* d_in, const int* in_sizes, int n_in,
                              void* d_out, int out_size)
{
    const float* x     = (const float*)d_in[0];
    const float* freqs = (const float*)d_in[1];
    const float* Wqkv  = (const float*)d_in[2];
    const float* Wout  = (const float*)d_in[3];
    float* out = (float*)d_out;

    float *x32, *wqt32, *wot32, *ao32, *qf, *kf;
    __nv_bfloat16 *vth, *vtl;
    cudaGetSymbolAddress((void**)&x32,   g_x32);
    cudaGetSymbolAddress((void**)&wqt32, g_wqt32);
    cudaGetSymbolAddress((void**)&wot32, g_wot32);
    cudaGetSymbolAddress((void**)&ao32,  g_ao32);
    cudaGetSymbolAddress((void**)&qf,  g_qf);
    cudaGetSymbolAddress((void**)&kf,  g_kf);
    cudaGetSymbolAddress((void**)&vth, g_vthi);
    cudaGetSymbolAddress((void**)&vtl, g_vtlo);

    cudaFuncSetAttribute(gemm_tf32,
                         cudaFuncAttributeMaxDynamicSharedMemorySize, GT_SMEM);
    cudaFuncSetAttribute(gemm_qkv_rope,
                         cudaFuncAttributeMaxDynamicSharedMemorySize, GT_SMEM);
    cudaFuncSetAttribute(attn_mma_kernel,
                         cudaFuncAttributeMaxDynamicSharedMemorySize, ATT_SMEM);

    // 1) tf32-rna prep
    rna_copy_kernel<<<(MT_ * D_ / 4 + 255) / 256, 256>>>(x, x32, MT_ * D_ / 4);
    transpose_rna_kernel<<<dim3(3 * D_ / 32, D_ / 32), dim3(32, 8)>>>(
        Wqkv, wqt32, D_, 3 * D_);
    transpose_rna_kernel<<<dim3(D_ / 32, D_ / 32), dim3(32, 8)>>>(
        Wout, wot32, D_, D_);

    // 2) QKV projection fused with RoPE + head split epilogue
    gemm_qkv_rope<<<dim3(3 * D_ / 128, MT_ / 128), 256, GT_SMEM>>>(
        x32, wqt32, freqs, qf, kf, vth, vtl);

    // 3) tensor-core causal flash attention (S tf32, PV bf16x3)
    attn_mma_kernel<<<dim3(T_ / 128, H_, B_), 256, ATT_SMEM>>>(
        qf, kf, vth, vtl, ao32);

    // 4) output projection (tf32)
    gemm_tf32<<<dim3(D_ / 128, MT_ / 128), 256, GT_SMEM>>>(
        ao32, wot32, out, MT_, D_, D_);
}

// round 17
// speedup vs baseline: 1.1058x; 1.0123x over previous
#include <cuda_runtime.h>
#include <cuda_bf16.h>
#include <math.h>
#include <stdint.h>

// Problem constants
#define B_  2
#define T_  2048
#define D_  2048
#define H_  16
#define DK_ 128
#define MT_ (B_ * T_)            // 4096 rows

// ---------------------------------------------------------------------------
// Scratch (static device globals; no allocation allowed)
// ---------------------------------------------------------------------------
__device__ float g_x32[(size_t)MT_ * D_];                  // x, tf32-rna
__device__ float g_wqt32[(size_t)3 * D_ * D_];             // Wqkv^T, tf32-rna
__device__ float g_wot32[(size_t)D_ * D_];                 // Wout^T, tf32-rna
__device__ float g_ao32[(size_t)MT_ * D_];                 // attn out, tf32-rna
__device__ float2 g_cs[(size_t)MT_ * 64];                  // (cos,sin) table

// attention operands
__device__ float g_qf[(size_t)B_ * H_ * T_ * DK_];            // Q tf32-rna [B,H,T,DK]
__device__ float g_kf[(size_t)B_ * H_ * T_ * DK_];            // K tf32-rna
__device__ __nv_bfloat16 g_vthi[(size_t)B_ * H_ * DK_ * T_];  // V^T hi [B,H,DK,T]
__device__ __nv_bfloat16 g_vtlo[(size_t)B_ * H_ * DK_ * T_];

// ---------------------------------------------------------------------------
// PTX helpers (baseline PTX only — harness PTX target is sm_103, no tcgen05)
// ---------------------------------------------------------------------------
__device__ __forceinline__ uint32_t smem_u32(const void* p) {
    uint32_t a;
    asm("{ .reg .u64 t; cvta.to.shared.u64 t, %1; cvt.u32.u64 %0, t; }"
        : "=r"(a) : "l"(p));
    return a;
}

#define CP16(dst, src) \
    asm volatile("cp.async.cg.shared.global [%0], [%1], 16;" :: "r"(dst), "l"(src))
#define CP_COMMIT() asm volatile("cp.async.commit_group;" ::: "memory")
#define CP_WAITG(n) asm volatile("cp.async.wait_group %0;" :: "n"(n) : "memory")

#define LDSM4(r0, r1, r2, r3, addr) \
    asm volatile("ldmatrix.sync.aligned.m8n8.x4.shared.b16 {%0,%1,%2,%3}, [%4];" \
                 : "=r"(r0), "=r"(r1), "=r"(r2), "=r"(r3) : "r"(addr))

#define MMA16816(c, a, b0, b1) \
    asm volatile("mma.sync.aligned.m16n8k16.row.col.f32.bf16.bf16.f32 " \
                 "{%0,%1,%2,%3}, {%4,%5,%6,%7}, {%8,%9}, {%0,%1,%2,%3};" \
                 : "+f"((c)[0]), "+f"((c)[1]), "+f"((c)[2]), "+f"((c)[3]) \
                 : "r"((a)[0]), "r"((a)[1]), "r"((a)[2]), "r"((a)[3]), \
                   "r"(b0), "r"(b1))

// NOTE: A regs r1/r2 from ldmatrix must be swapped for the tf32 fragment
// (ldmatrix gives a0,a2,a1,a3 with our addressing).
#define MMA1688TF_SW(c, a, b0, b1) \
    asm volatile("mma.sync.aligned.m16n8k8.row.col.f32.tf32.tf32.f32 " \
                 "{%0,%1,%2,%3}, {%4,%5,%6,%7}, {%8,%9}, {%0,%1,%2,%3};" \
                 : "+f"((c)[0]), "+f"((c)[1]), "+f"((c)[2]), "+f"((c)[3]) \
                 : "r"((a)[0]), "r"((a)[2]), "r"((a)[1]), "r"((a)[3]), \
                   "r"(b0), "r"(b1))

__device__ __forceinline__ float rna_tf32(float x) {
    uint32_t r, i = __float_as_uint(x);
    asm("cvt.rna.tf32.f32 %0, %1;" : "=r"(r) : "r"(i));
    return __uint_as_float(r);
}

// Hardware MUFU exp2 (1 instruction). Args are <= 0 or -inf (-inf -> 0). Safe.
__device__ __forceinline__ float ex2a(float x) {
    float r;
    asm("ex2.approx.f32 %0, %1;" : "=f"(r) : "f"(x));
    return r;
}

// ---------------------------------------------------------------------------
// Precision split helpers
// ---------------------------------------------------------------------------
__device__ __forceinline__ void split_one(float x, __nv_bfloat16& h, __nv_bfloat16& l) {
    h = __float2bfloat16_rn(x);
    l = __float2bfloat16_rn(x - __bfloat162float(h));
}

__device__ __forceinline__ void split2pack(float a, float b, uint32_t& hr, uint32_t& lr) {
    __nv_bfloat16 ah = __float2bfloat16_rn(a);
    __nv_bfloat16 bh = __float2bfloat16_rn(b);
    __nv_bfloat16 al = __float2bfloat16_rn(a - __bfloat162float(ah));
    __nv_bfloat16 bl = __float2bfloat16_rn(b - __bfloat162float(bh));
    __nv_bfloat162 hv; hv.x = ah; hv.y = bh;
    __nv_bfloat162 lv; lv.x = al; lv.y = bl;
    hr = *reinterpret_cast<uint32_t*>(&hv);
    lr = *reinterpret_cast<uint32_t*>(&lv);
}

// Elementwise tf32-rna copy
__global__ __launch_bounds__(256) void rna_copy_kernel(
    const float* __restrict__ X, float* __restrict__ Y, int n4)
{
    int i = blockIdx.x * blockDim.x + threadIdx.x;
    if (i >= n4) return;
    float4 v = *(const float4*)&X[(size_t)i * 4];
    v.x = rna_tf32(v.x); v.y = rna_tf32(v.y);
    v.z = rna_tf32(v.z); v.w = rna_tf32(v.w);
    *(float4*)&Y[(size_t)i * 4] = v;
}

// Precompute (cos,sin) for all (row, j): identical sincosf values as before.
__global__ __launch_bounds__(256) void cs_table_kernel(
    const float* __restrict__ freqs, float2* __restrict__ CS, int n)
{
    int i = blockIdx.x * blockDim.x + threadIdx.x;
    if (i >= n) return;
    float s, c;
    sincosf(freqs[i], &s, &c);
    CS[i] = make_float2(c, s);
}

// Transpose + rna: W[K,N] fp32 row-major -> W^T[N,K] tf32-rna fp32
__global__ __launch_bounds__(256) void transpose_rna_kernel(
    const float* __restrict__ W, float* __restrict__ Wt, int K, int N)
{
    __shared__ float t[32][33];
    const int n0 = blockIdx.x * 32, k0 = blockIdx.y * 32;
    const int tx = threadIdx.x, ty = threadIdx.y;   // 32 x 8
#pragma unroll
    for (int i = 0; i < 4; i++)
        t[ty + 8 * i][tx] = W[(size_t)(k0 + ty + 8 * i) * N + n0 + tx];
    __syncthreads();
#pragma unroll
    for (int i = 0; i < 4; i++)
        Wt[(size_t)(n0 + ty + 8 * i) * K + k0 + tx] = rna_tf32(t[tx][ty + 8 * i]);
}

// ---------------------------------------------------------------------------
// Shared GEMM tile machinery (R6-validated)
// ---------------------------------------------------------------------------
#define GT_STAGES 3
#define GT_ROW_BYTES 144
#define GT_MAT_BYTES (128 * GT_ROW_BYTES)          // 18432
#define GT_STAGE_BYTES (2 * GT_MAT_BYTES)          // 36864
#define GT_SMEM (GT_STAGES * GT_STAGE_BYTES)       // 110592

__device__ __forceinline__ void gt_load_stage(
    uint32_t sbase, const float* __restrict__ A, const float* __restrict__ Bm,
    int m0, int n0, int K, int kb, int tid)
{
#pragma unroll
    for (int i = 0; i < 8; i++) {
        const int idx = tid + 256 * i;          // 0..2047
        const int row = (idx >> 3) & 127;       // 0..127
        const int mat = idx >> 10;              // 0: A, 1: B
        const int seg = idx & 7;                // 16B segment (4 floats)
        const uint32_t d = (uint32_t)(mat * GT_MAT_BYTES + row * GT_ROW_BYTES + seg * 16);
        const float* src = (mat == 0)
            ? (A  + (size_t)(m0 + row) * K + kb + seg * 4)
            : (Bm + (size_t)(n0 + row) * K + kb + seg * 4);
        CP16(sbase + d, src);
    }
}

// Mainloop body shared by both GEMM kernels: accumulates the 128x128 CTA tile.
__device__ __forceinline__ void gt_mainloop(
    uint32_t sbase, const float* __restrict__ A, const float* __restrict__ Bm,
    int m0, int n0, int K, int tid, int wm, int wn,
    uint32_t rowsel, uint32_t quad, float acc[4][4][4])
{
#pragma unroll
    for (int mt = 0; mt < 4; mt++)
#pragma unroll
        for (int nt = 0; nt < 4; nt++)
#pragma unroll
            for (int e = 0; e < 4; e++) acc[mt][nt][e] = 0.f;

    const int nk = K / 32;

#pragma unroll
    for (int s = 0; s < GT_STAGES - 1; s++) {
        gt_load_stage(sbase + s * GT_STAGE_BYTES, A, Bm, m0, n0, K, s * 32, tid);
        CP_COMMIT();
    }

    for (int kb = 0; kb < nk; kb++) {
        CP_WAITG(GT_STAGES - 2);
        __syncthreads();

        if (kb + GT_STAGES - 1 < nk) {
            gt_load_stage(sbase + ((kb + GT_STAGES - 1) % GT_STAGES) * GT_STAGE_BYTES,
                          A, Bm, m0, n0, K, (kb + GT_STAGES - 1) * 32, tid);
        }
        CP_COMMIT();

        const uint32_t aS = sbase + (kb % GT_STAGES) * GT_STAGE_BYTES;
        const uint32_t bS = aS + GT_MAT_BYTES;

#pragma unroll
        for (int s = 0; s < 4; s++) {          // 4 k8 steps in BK=32
            uint32_t bf[2][4];
#pragma unroll
            for (int np = 0; np < 2; np++) {
                const uint32_t boff =
                    (uint32_t)((wn + np * 16 + rowsel) * GT_ROW_BYTES + quad + s * 32);
                LDSM4(bf[np][0], bf[np][1], bf[np][2], bf[np][3], bS + boff);
            }
#pragma unroll
            for (int mt = 0; mt < 4; mt++) {
                const uint32_t aoff =
                    (uint32_t)((wm + mt * 16 + rowsel) * GT_ROW_BYTES + quad + s * 32);
                uint32_t af[4];
                LDSM4(af[0], af[1], af[2], af[3], aS + aoff);
#pragma unroll
                for (int nt = 0; nt < 4; nt++) {
                    MMA1688TF_SW(acc[mt][nt], af,
                                 bf[nt >> 1][(nt & 1) * 2],
                                 bf[nt >> 1][(nt & 1) * 2 + 1]);
                }
            }
        }
    }
}

// ---------------------------------------------------------------------------
// Plain TF32 GEMM (out projection): C[M,N] = A[M,K] @ B[N,K]^T
// ---------------------------------------------------------------------------
__global__ __launch_bounds__(256, 2) void gemm_tf32(
    const float* __restrict__ A, const float* __restrict__ Bm,
    float* __restrict__ C, int M, int N, int K)
{
    extern __shared__ char dsm[];
    const uint32_t sbase = smem_u32(dsm);

    const int tid  = threadIdx.x;
    const int wid  = tid >> 5;
    const int lane = tid & 31;
    const int m0 = blockIdx.y * 128;
    const int n0 = blockIdx.x * 128;
    const int wm = (wid & 1) * 64;
    const int wn = (wid >> 1) * 32;
    const uint32_t lr   = lane & 7;
    const uint32_t lmat = lane >> 3;
    const uint32_t rowsel = (lmat >> 1) * 8 + lr;
    const uint32_t quad   = (lmat & 1) * 16;

    float acc[4][4][4];
    gt_mainloop(sbase, A, Bm, m0, n0, K, tid, wm, wn, rowsel, quad, acc);

    const int r0 = lane >> 2;
    const int c0 = (lane & 3) * 2;
#pragma unroll
    for (int mt = 0; mt < 4; mt++) {
#pragma unroll
        for (int nt = 0; nt < 4; nt++) {
            const int row = m0 + wm + mt * 16 + r0;
            const int col = n0 + wn + nt * 8 + c0;
            float2 v0; v0.x = acc[mt][nt][0]; v0.y = acc[mt][nt][1];
            float2 v1; v1.x = acc[mt][nt][2]; v1.y = acc[mt][nt][3];
            *(float2*)&C[(size_t)row * N + col]       = v0;
            *(float2*)&C[(size_t)(row + 8) * N + col] = v1;
        }
    }
}

// ---------------------------------------------------------------------------
// Fused QKV GEMM + RoPE epilogue (cos/sin from precomputed table).
// N-tiles (128 wide) align exactly with q/k/v chunks (384 = 3*128 per head):
//   tile_type = (n0/128) % 3  (0=q, 1=k, 2=v),  h = n0/384.
// Accumulator threads hold adjacent column pairs (2j, 2j+1) = RoPE pairs.
// q,k: rotate + tf32-rna -> Qf/Kf [B,H,T,DK].
// v:   bf16 hi/lo split -> Vth/Vtl [B,H,DK,T] (transposed).
// ---------------------------------------------------------------------------
__global__ __launch_bounds__(256, 2) void gemm_qkv_rope(
    const float* __restrict__ A, const float* __restrict__ Bm,
    const float2* __restrict__ CS,
    float* __restrict__ Qf, float* __restrict__ Kf,
    __nv_bfloat16* __restrict__ Vth, __nv_bfloat16* __restrict__ Vtl)
{
    extern __shared__ char dsm[];
    const uint32_t sbase = smem_u32(dsm);

    const int K = D_;
    const int tid  = threadIdx.x;
    const int wid  = tid >> 5;
    const int lane = tid & 31;
    const int m0 = blockIdx.y * 128;
    const int n0 = blockIdx.x * 128;
    const int wm = (wid & 1) * 64;
    const int wn = (wid >> 1) * 32;
    const uint32_t lr   = lane & 7;
    const uint32_t lmat = lane >> 3;
    const uint32_t rowsel = (lmat >> 1) * 8 + lr;
    const uint32_t quad   = (lmat & 1) * 16;

    float acc[4][4][4];
    gt_mainloop(sbase, A, Bm, m0, n0, K, tid, wm, wn, rowsel, quad, acc);

    const int tt = (n0 >> 7) % 3;            // 0=q, 1=k, 2=v
    const int h  = n0 / 384;
    const int r0 = lane >> 2;
    const int c0 = (lane & 3) * 2;

    if (tt < 2) {
        float* dst = (tt == 0) ? Qf : Kf;
#pragma unroll
        for (int mt = 0; mt < 4; mt++) {
#pragma unroll
            for (int nt = 0; nt < 4; nt++) {
                const int lc = wn + nt * 8 + c0;     // 0..126 even
                const int j  = lc >> 1;
#pragma unroll
                for (int half = 0; half < 2; half++) {
                    const int row = m0 + wm + mt * 16 + r0 + half * 8;
                    const int b = row >> 11;         // row / T_
                    const int t = row & (T_ - 1);
                    const float2 cs = CS[(size_t)row * 64 + j];
                    const float v0 = acc[mt][nt][half * 2];
                    const float v1 = acc[mt][nt][half * 2 + 1];
                    float2 o;
                    o.x = rna_tf32(v0 * cs.x - v1 * cs.y);
                    o.y = rna_tf32(v0 * cs.y + v1 * cs.x);
                    const size_t ob =
                        (((size_t)(b * H_ + h)) * T_ + t) * DK_ + lc;
                    *(float2*)&dst[ob] = o;
                }
            }
        }
    } else {
#pragma unroll
        for (int mt = 0; mt < 4; mt++) {
#pragma unroll
            for (int nt = 0; nt < 4; nt++) {
                const int lc = wn + nt * 8 + c0;
#pragma unroll
                for (int half = 0; half < 2; half++) {
                    const int row = m0 + wm + mt * 16 + r0 + half * 8;
                    const int b = row >> 11;
                    const int t = row & (T_ - 1);
                    const size_t vb =
                        ((size_t)(b * H_ + h) * DK_ + lc) * T_ + t;
                    __nv_bfloat16 vh, vl;
                    split_one(acc[mt][nt][half * 2], vh, vl);
                    Vth[vb] = vh;  Vtl[vb] = vl;
                    split_one(acc[mt][nt][half * 2 + 1], vh, vl);
                    Vth[vb + T_] = vh;  Vtl[vb + T_] = vl;
                }
            }
        }
    }
}

// ---------------------------------------------------------------------------
// Tensor-core flash attention (causal).
// S = Q K^T single-pass tf32; O += P V bf16x3; MUFU softmax.
// qt is REVERSED vs blockIdx.x so heaviest CTAs launch first.
// ---------------------------------------------------------------------------
#define AQ4_STRIDE 528           // 128 fp32 = 512B + 16 pad
#define AV_STRIDE  144           // 64 bf16 = 128B + 16 pad
#define A_Q     0                // 128 * 528 = 67584
#define A_KBASE 67584            // per stage 64 * 528 = 33792, x2
#define A_KSTAGE 33792
#define A_VBASE 135168           // per stage: hi 18432 + lo 18432 = 36864, x2
#define A_VHALF 18432
#define A_VSTAGE 36864
#define ATT_SMEM 208896

__device__ __forceinline__ void att_load_kv(
    uint32_t sb, int stage, int kt, int bh, int tid,
    const float* __restrict__ Kf,
    const __nv_bfloat16* __restrict__ Vth, const __nv_bfloat16* __restrict__ Vtl)
{
    const uint32_t kb = sb + A_KBASE + stage * A_KSTAGE;
    const uint32_t vb = sb + A_VBASE + stage * A_VSTAGE;
    const float* kg = Kf + ((size_t)bh * T_ + kt * 64) * DK_;
#pragma unroll
    for (int i = 0; i < 8; i++) {
        const int idx = tid + 256 * i;          // 0..2047
        const int row = idx >> 5, seg = idx & 31;
        CP16(kb + (uint32_t)(row * AQ4_STRIDE + seg * 16),
             kg + (size_t)row * DK_ + seg * 4);
    }
    const __nv_bfloat16* vhg = Vth + (size_t)bh * DK_ * T_ + (size_t)kt * 64;
    const __nv_bfloat16* vlg = Vtl + (size_t)bh * DK_ * T_ + (size_t)kt * 64;
#pragma unroll
    for (int i = 0; i < 4; i++) {
        const int idx = tid + 256 * i;          // 0..1023
        const int row = idx >> 3, seg = idx & 7;
        const uint32_t d = (uint32_t)(row * AV_STRIDE + seg * 16);
        CP16(vb + d,            vhg + (size_t)row * T_ + seg * 8);
        CP16(vb + A_VHALF + d,  vlg + (size_t)row * T_ + seg * 8);
    }
}

__global__ __launch_bounds__(256, 1) void attn_mma_kernel(
    const float* __restrict__ Qf, const float* __restrict__ Kf,
    const __nv_bfloat16* __restrict__ Vth, const __nv_bfloat16* __restrict__ Vtl,
    float* __restrict__ AO)
{
    extern __shared__ char asm_[];
    const uint32_t sb = smem_u32(asm_);

    const int qt = (gridDim.x - 1) - blockIdx.x;   // heaviest tiles first
    const int h = blockIdx.y, b = blockIdx.z;
    const int bh = b * H_ + h;
    const int q0 = qt * 128;
    const int tid = threadIdx.x, wid = tid >> 5, lane = tid & 31;
    const uint32_t lr = lane & 7, lmat = lane >> 3;
    const uint32_t rowsel = (lmat >> 1) * 8 + lr;
    const uint32_t quad   = (lmat & 1) * 16;

    // ---- prologue: load Q (fp32) + stage 0 K/V ----
    {
        const float* qg = Qf + ((size_t)bh * T_ + q0) * DK_;
#pragma unroll
        for (int i = 0; i < 16; i++) {
            const int idx = tid + 256 * i;      // 0..4095
            const int row = idx >> 5, seg = idx & 31;
            CP16(sb + A_Q + (uint32_t)(row * AQ4_STRIDE + seg * 16),
                 qg + (size_t)row * DK_ + seg * 4);
        }
        att_load_kv(sb, 0, 0, bh, tid, Kf, Vth, Vtl);
        CP_COMMIT();
    }

    float oacc[16][4];
#pragma unroll
    for (int nt = 0; nt < 16; nt++)
#pragma unroll
        for (int e = 0; e < 4; e++) oacc[nt][e] = 0.f;
    float m0 = -INFINITY, m1 = -INFINITY, l0 = 0.f, l1 = 0.f;
    const float csc = 0.08838834764831845f * 1.44269504089f;

    const int nkt = 2 * qt + 2;
    const int rowg0 = q0 + wid * 16 + (lane >> 2);
    const int rowg1 = rowg0 + 8;

    for (int kt = 0; kt < nkt; kt++) {
        if (kt + 1 < nkt) {
            att_load_kv(sb, (kt + 1) & 1, kt + 1, bh, tid, Kf, Vth, Vtl);
            CP_COMMIT();
            CP_WAITG(1);
        } else {
            CP_WAITG(0);
        }
        __syncthreads();

        const uint32_t kS  = sb + A_KBASE + (kt & 1) * A_KSTAGE;
        const uint32_t vbh = sb + A_VBASE + (kt & 1) * A_VSTAGE;
        const uint32_t vbl = vbh + A_VHALF;

        // ---- S = Q K^T (single-pass tf32) ----
        float sacc[8][4];
#pragma unroll
        for (int nt = 0; nt < 8; nt++)
#pragma unroll
            for (int e = 0; e < 4; e++) sacc[nt][e] = 0.f;

#pragma unroll
        for (int ks = 0; ks < 16; ks++) {      // 16 k8 steps over DK=128
            uint32_t af[4];
            LDSM4(af[0], af[1], af[2], af[3],
                  sb + A_Q + (uint32_t)((wid * 16 + rowsel) * AQ4_STRIDE +
                                        quad + ks * 32));
            uint32_t bf[4][4];
#pragma unroll
            for (int np = 0; np < 4; np++) {
                LDSM4(bf[np][0], bf[np][1], bf[np][2], bf[np][3],
                      kS + (uint32_t)((np * 16 + rowsel) * AQ4_STRIDE +
                                      quad + ks * 32));
            }
#pragma unroll
            for (int nt = 0; nt < 8; nt++) {
                MMA1688TF_SW(sacc[nt], af,
                             bf[nt >> 1][(nt & 1) * 2],
                             bf[nt >> 1][(nt & 1) * 2 + 1]);
            }
        }

        // ---- scale (+ causal mask on boundary tiles), log2 domain ----
        const bool need_mask = (kt >= 2 * qt);
#pragma unroll
        for (int nt = 0; nt < 8; nt++) {
            const int col = kt * 64 + nt * 8 + (lane & 3) * 2;
#pragma unroll
            for (int e = 0; e < 4; e++) {
                float z = sacc[nt][e] * csc;
                if (need_mask) {
                    const int cc = col + (e & 1);
                    const int rr = (e < 2) ? rowg0 : rowg1;
                    if (cc > rr) z = -INFINITY;
                }
                sacc[nt][e] = z;
            }
        }

        // ---- online softmax (MUFU) ----
        float mx0 = -INFINITY, mx1 = -INFINITY;
#pragma unroll
        for (int nt = 0; nt < 8; nt++) {
            mx0 = fmaxf(mx0, fmaxf(sacc[nt][0], sacc[nt][1]));
            mx1 = fmaxf(mx1, fmaxf(sacc[nt][2], sacc[nt][3]));
        }
        mx0 = fmaxf(mx0, __shfl_xor_sync(0xffffffffu, mx0, 1));
        mx0 = fmaxf(mx0, __shfl_xor_sync(0xffffffffu, mx0, 2));
        mx1 = fmaxf(mx1, __shfl_xor_sync(0xffffffffu, mx1, 1));
        mx1 = fmaxf(mx1, __shfl_xor_sync(0xffffffffu, mx1, 2));
        const float mn0 = fmaxf(m0, mx0), mn1 = fmaxf(m1, mx1);
        const float al0 = ex2a(m0 - mn0), al1 = ex2a(m1 - mn1);
        float rs0 = 0.f, rs1 = 0.f;
#pragma unroll
        for (int nt = 0; nt < 8; nt++) {
            sacc[nt][0] = ex2a(sacc[nt][0] - mn0);
            sacc[nt][1] = ex2a(sacc[nt][1] - mn0);
            sacc[nt][2] = ex2a(sacc[nt][2] - mn1);
            sacc[nt][3] = ex2a(sacc[nt][3] - mn1);
            rs0 += sacc[nt][0] + sacc[nt][1];
            rs1 += sacc[nt][2] + sacc[nt][3];
        }
        rs0 += __shfl_xor_sync(0xffffffffu, rs0, 1);
        rs0 += __shfl_xor_sync(0xffffffffu, rs0, 2);
        rs1 += __shfl_xor_sync(0xffffffffu, rs1, 1);
        rs1 += __shfl_xor_sync(0xffffffffu, rs1, 2);
        l0 = l0 * al0 + rs0;  m0 = mn0;
        l1 = l1 * al1 + rs1;  m1 = mn1;
#pragma unroll
        for (int nt = 0; nt < 16; nt++) {
            oacc[nt][0] *= al0; oacc[nt][1] *= al0;
            oacc[nt][2] *= al1; oacc[nt][3] *= al1;
        }

        // ---- pack P into bf16 A-fragments (hi/lo) ----
        uint32_t pah[4][4], pal[4][4];
#pragma unroll
        for (int ck = 0; ck < 4; ck++) {
            split2pack(sacc[2 * ck][0],     sacc[2 * ck][1],     pah[ck][0], pal[ck][0]);
            split2pack(sacc[2 * ck][2],     sacc[2 * ck][3],     pah[ck][1], pal[ck][1]);
            split2pack(sacc[2 * ck + 1][0], sacc[2 * ck + 1][1], pah[ck][2], pal[ck][2]);
            split2pack(sacc[2 * ck + 1][2], sacc[2 * ck + 1][3], pah[ck][3], pal[ck][3]);
        }

        // ---- O += P V (bf16x3) ----
#pragma unroll
        for (int ck = 0; ck < 4; ck++) {
#pragma unroll
            for (int nh = 0; nh < 8; nh++) {
                const uint32_t boff =
                    (uint32_t)((nh * 16 + (lmat >> 1) * 8 + lr) * AV_STRIDE +
                               (lmat & 1) * 16 + ck * 32);
                uint32_t vh[4], vl[4];
                LDSM4(vh[0], vh[1], vh[2], vh[3], vbh + boff);
                LDSM4(vl[0], vl[1], vl[2], vl[3], vbl + boff);
#pragma unroll
                for (int sub = 0; sub < 2; sub++) {
                    const int nt = nh * 2 + sub;
                    const uint32_t b0h = vh[sub * 2], b1h = vh[sub * 2 + 1];
                    const uint32_t b0l = vl[sub * 2], b1l = vl[sub * 2 + 1];
                    MMA16816(oacc[nt], pah[ck], b0h, b1h);
                    MMA16816(oacc[nt], pah[ck], b0l, b1l);
                    MMA16816(oacc[nt], pal[ck], b0h, b1h);
                }
            }
        }
        __syncthreads();
    }

    // ---- epilogue: normalize, tf32-rna, write fp32 [B,T,D] ----
    const float inv0 = 1.f / l0, inv1 = 1.f / l1;
#pragma unroll
    for (int nt = 0; nt < 16; nt++) {
        const int col = h * DK_ + nt * 8 + (lane & 3) * 2;
        const size_t o0 = ((size_t)b * T_ + rowg0) * D_ + col;
        const size_t o1 = ((size_t)b * T_ + rowg1) * D_ + col;
        float2 v0;
        v0.x = rna_tf32(oacc[nt][0] * inv0);
        v0.y = rna_tf32(oacc[nt][1] * inv0);
        float2 v1;
        v1.x = rna_tf32(oacc[nt][2] * inv1);
        v1.y = rna_tf32(oacc[nt][3] * inv1);
        *(float2*)&AO[o0] = v0;
        *(float2*)&AO[o1] = v1;
    }
}

// ---------------------------------------------------------------------------
// Launch
// ---------------------------------------------------------------------------
extern "C" void kernel_launch(void* const* d_in, const int* in_sizes, int n_in,
                              void* d_out, int out_size)
{
    const float* x     = (const float*)d_in[0];
    const float* freqs = (const float*)d_in[1];
    const float* Wqkv  = (const float*)d_in[2];
    const float* Wout  = (const float*)d_in[3];
    float* out = (float*)d_out;

    float *x32, *wqt32, *wot32, *ao32, *qf, *kf;
    float2* cs;
    __nv_bfloat16 *vth, *vtl;
    cudaGetSymbolAddress((void**)&x32,   g_x32);
    cudaGetSymbolAddress((void**)&wqt32, g_wqt32);
    cudaGetSymbolAddress((void**)&wot32, g_wot32);
    cudaGetSymbolAddress((void**)&ao32,  g_ao32);
    cudaGetSymbolAddress((void**)&cs,    g_cs);
    cudaGetSymbolAddress((void**)&qf,  g_qf);
    cudaGetSymbolAddress((void**)&kf,  g_kf);
    cudaGetSymbolAddress((void**)&vth, g_vthi);
    cudaGetSymbolAddress((void**)&vtl, g_vtlo);

    cudaFuncSetAttribute(gemm_tf32,
                         cudaFuncAttributeMaxDynamicSharedMemorySize, GT_SMEM);
    cudaFuncSetAttribute(gemm_qkv_rope,
                         cudaFuncAttributeMaxDynamicSharedMemorySize, GT_SMEM);
    cudaFuncSetAttribute(attn_mma_kernel,
                         cudaFuncAttributeMaxDynamicSharedMemorySize, ATT_SMEM);

    // 1) tf32-rna prep + cos/sin table
    rna_copy_kernel<<<(MT_ * D_ / 4 + 255) / 256, 256>>>(x, x32, MT_ * D_ / 4);
    transpose_rna_kernel<<<dim3(3 * D_ / 32, D_ / 32), dim3(32, 8)>>>(
        Wqkv, wqt32, D_, 3 * D_);
    transpose_rna_kernel<<<dim3(D_ / 32, D_ / 32), dim3(32, 8)>>>(
        Wout, wot32, D_, D_);
    cs_table_kernel<<<(MT_ * 64 + 255) / 256, 256>>>(freqs, cs, MT_ * 64);

    // 2) QKV projection fused with RoPE + head split epilogue
    gemm_qkv_rope<<<dim3(3 * D_ / 128, MT_ / 128), 256, GT_SMEM>>>(
        x32, wqt32, cs, qf, kf, vth, vtl);

    // 3) tensor-core causal flash attention (S tf32, PV bf16x3)
    attn_mma_kernel<<<dim3(T_ / 128, H_, B_), 256, ATT_SMEM>>>(
        qf, kf, vth, vtl, ao32);

    // 4) output projection (tf32)
    gemm_tf32<<<dim3(D_ / 128, MT_ / 128), 256, GT_SMEM>>>(
        ao32, wot32, out, MT_, D_, D_);
}